// round 3
// baseline (speedup 1.0000x reference)
#include <cuda_runtime.h>
#include <math.h>

// Problem constants (fixed shapes)
#define E      768
#define H      12
#define NW     8
#define DK     64
#define KFEAT  16            // 8 cos + 8 sin features
#define KROWS  17            // + bias row
#define PN     (KROWS * E)   // 13056 folded-weight elements

#define TOK_PER_BLK 64
#define MAIN_THREADS 128
#define NSLAB   3
#define SLAB    (E / NSLAB)     // 256 columns per slab

#define RCHUNKS 24
#define RCHUNK  (E / RCHUNKS)   // 32

// Scratch (device globals: allocation-free rule)
__device__ __align__(16) float g_R[PN];                 // folded weights   [17][768] over e
__device__ __align__(16) float g_part[RCHUNKS * PN];    // deterministic partial sums

// ---------------------------------------------------------------------------
// packed fp32x2 helpers (PTX-only, sm_100+)
// ---------------------------------------------------------------------------
__device__ __forceinline__ unsigned long long fma2(unsigned long long a,
                                                   unsigned long long b,
                                                   unsigned long long c) {
    unsigned long long d;
    asm("fma.rn.f32x2 %0, %1, %2, %3;" : "=l"(d) : "l"(a), "l"(b), "l"(c));
    return d;
}
__device__ __forceinline__ unsigned long long mul2(unsigned long long a,
                                                   unsigned long long b) {
    unsigned long long d;
    asm("mul.rn.f32x2 %0, %1, %2;" : "=l"(d) : "l"(a), "l"(b));
    return d;
}
__device__ __forceinline__ unsigned long long add2(unsigned long long a,
                                                   unsigned long long b) {
    unsigned long long d;
    asm("add.rn.f32x2 %0, %1, %2;" : "=l"(d) : "l"(a), "l"(b));
    return d;
}
__device__ __forceinline__ unsigned long long pack2(float v) {
    unsigned long long d;
    asm("mov.b64 %0, {%1, %1};" : "=l"(d) : "f"(v));
    return d;
}
__device__ __forceinline__ void stcs64(void* p, unsigned long long v) {
    asm volatile("st.global.cs.b64 [%0], %1;" :: "l"(p), "l"(v) : "memory");
}

// ---------------------------------------------------------------------------
// Kernel A (fused build_P + fold): partial R = P @ W_out over r-chunks.
//   P[k][r], r = h*64+d:
//     k in [0,8):   cos(theta[h][k])    * W_proj[h][k][d]
//     k in [8,16): -sin(theta[h][k-8])  * W_proj[h][k-8][d]
//     k == 16:      b_proj[r]
//   grid (E/128 = 6 e-chunks, RCHUNKS r-chunks), 128 threads
// ---------------------------------------------------------------------------
__global__ void fold_R_partial_kernel(const float* __restrict__ theta,
                                      const float* __restrict__ W_proj,
                                      const float* __restrict__ b_proj,
                                      const float* __restrict__ W_out) {
    __shared__ float Ps[KROWS][RCHUNK];
    const int e  = blockIdx.x * 128 + threadIdx.x;
    const int r0 = blockIdx.y * RCHUNK;

    // Build the P slab in-block (KROWS*RCHUNK = 544 entries)
    for (int idx = threadIdx.x; idx < KROWS * RCHUNK; idx += 128) {
        int k  = idx / RCHUNK;
        int rr = idx - k * RCHUNK;
        int r  = r0 + rr;
        int h  = r >> 6;
        int d  = r & 63;
        float v;
        if (k < 8) {
            v = cosf(theta[h * NW + k]) * W_proj[(h * NW + k) * DK + d];
        } else if (k < 16) {
            int w = k - 8;
            v = -sinf(theta[h * NW + w]) * W_proj[(h * NW + w) * DK + d];
        } else {
            v = b_proj[r];
        }
        Ps[k][rr] = v;
    }
    __syncthreads();

    float acc[KROWS];
#pragma unroll
    for (int k = 0; k < KROWS; k++) acc[k] = 0.f;

#pragma unroll 8
    for (int rr = 0; rr < RCHUNK; rr++) {
        float wo = __ldg(&W_out[(size_t)(r0 + rr) * E + e]);
#pragma unroll
        for (int k = 0; k < KROWS; k++) acc[k] = fmaf(Ps[k][rr], wo, acc[k]);
    }

    float* dst = g_part + (size_t)blockIdx.y * PN;
#pragma unroll
    for (int k = 0; k < KROWS; k++) dst[k * E + e] = acc[k];
}

// ---------------------------------------------------------------------------
// Kernel B: reduce partials (+ b_out into bias row)
// ---------------------------------------------------------------------------
__global__ void reduce_R_kernel(const float* __restrict__ b_out) {
    int i = blockIdx.x * blockDim.x + threadIdx.x;
    if (i >= PN) return;
    float s = 0.f;
#pragma unroll
    for (int j = 0; j < RCHUNKS; j++) s += g_part[(size_t)j * PN + i];
    if (i >= 16 * E) s += b_out[i - 16 * E];
    g_R[i] = s;
}

// ---------------------------------------------------------------------------
// Main kernel: per token 8 sincos, then [ntok,16] @ R[16,768] + bias
//   grid (ntok/64, 3 column-slabs), 128 threads.
//   Each thread owns ONE column-pair (c, c+1): 17 packed weights in regs.
//   Features stored pre-duplicated (f32x2) in smem -> no per-FMA pack MOVs.
// ---------------------------------------------------------------------------
__global__ void __launch_bounds__(MAIN_THREADS, 6)
qattn_main_kernel(const float* __restrict__ x, float* __restrict__ out) {
    __shared__ unsigned long long s_cs2[TOK_PER_BLK][KFEAT];   // 8 KB

    const int tid   = threadIdx.x;
    const long tok0 = (long)blockIdx.x * TOK_PER_BLK;

    // ---- Phase 1: sincos of x[:, :8] for this token tile (pre-packed) ----
    {
        int t    = tid >> 1;         // 0..63
        int half = tid & 1;          // 0..1
        const float4 xv = *(const float4*)(x + (size_t)(tok0 + t) * E + half * 4);
        float s, c;
        int w0 = half * 4;
        sincosf(xv.x, &s, &c); s_cs2[t][w0 + 0] = pack2(c); s_cs2[t][8 + w0 + 0] = pack2(s);
        sincosf(xv.y, &s, &c); s_cs2[t][w0 + 1] = pack2(c); s_cs2[t][8 + w0 + 1] = pack2(s);
        sincosf(xv.z, &s, &c); s_cs2[t][w0 + 2] = pack2(c); s_cs2[t][8 + w0 + 2] = pack2(s);
        sincosf(xv.w, &s, &c); s_cs2[t][w0 + 3] = pack2(c); s_cs2[t][8 + w0 + 3] = pack2(s);
    }

    // ---- Phase 2: this thread's column-pair weights into registers ----
    const int c = blockIdx.y * SLAB + 2 * tid;
    unsigned long long w[KROWS];
#pragma unroll
    for (int k = 0; k < KROWS; k++)
        w[k] = *(const unsigned long long*)(g_R + k * E + c);

    __syncthreads();

    // ---- Token loop: 8x broadcast LDS.128 + 16 FFMA2 + 1 STG.64 ----
    float* op = out + (size_t)tok0 * E + c;
#pragma unroll 2
    for (int t = 0; t < TOK_PER_BLK; t++) {
        const ulonglong2* ap = (const ulonglong2*)s_cs2[t];

        ulonglong2 v0 = ap[0], v1 = ap[1], v2 = ap[2], v3 = ap[3];
        unsigned long long acc0 = fma2(v0.x, w[0], w[16]);   // bias folded into chain 0
        unsigned long long acc1 = mul2(v0.y, w[1]);
        acc0 = fma2(v1.x, w[2], acc0);
        acc1 = fma2(v1.y, w[3], acc1);
        acc0 = fma2(v2.x, w[4], acc0);
        acc1 = fma2(v2.y, w[5], acc1);
        acc0 = fma2(v3.x, w[6], acc0);
        acc1 = fma2(v3.y, w[7], acc1);

        ulonglong2 v4 = ap[4], v5 = ap[5], v6 = ap[6], v7 = ap[7];
        acc0 = fma2(v4.x, w[8],  acc0);
        acc1 = fma2(v4.y, w[9],  acc1);
        acc0 = fma2(v5.x, w[10], acc0);
        acc1 = fma2(v5.y, w[11], acc1);
        acc0 = fma2(v6.x, w[12], acc0);
        acc1 = fma2(v6.y, w[13], acc1);
        acc0 = fma2(v7.x, w[14], acc0);
        acc1 = fma2(v7.y, w[15], acc1);

        stcs64(op, add2(acc0, acc1));
        op += E;
    }
}

// ---------------------------------------------------------------------------
// Launch
// inputs (metadata order): x[B,S,E] f32, theta[H,NW] f32, W_proj[H,NW,DK] f32,
//                          b_proj[H,DK] f32, W_out[E,E] f32, b_out[E] f32
// output: [B,S,E] f32
// ---------------------------------------------------------------------------
extern "C" void kernel_launch(void* const* d_in, const int* in_sizes, int n_in,
                              void* d_out, int out_size) {
    const float* x      = (const float*)d_in[0];
    const float* theta  = (const float*)d_in[1];
    const float* W_proj = (const float*)d_in[2];
    const float* b_proj = (const float*)d_in[3];
    const float* W_out  = (const float*)d_in[4];
    const float* b_out  = (const float*)d_in[5];
    float* out = (float*)d_out;

    const int ntok = in_sizes[0] / E;               // B*S = 32768

    // Prologue: fold weights (recomputed every call — deterministic)
    fold_R_partial_kernel<<<dim3(E / 128, RCHUNKS), 128>>>(theta, W_proj, b_proj, W_out);
    reduce_R_kernel<<<(PN + 255) / 256, 256>>>(b_out);

    // Main pass
    qattn_main_kernel<<<dim3(ntok / TOK_PER_BLK, NSLAB), MAIN_THREADS>>>(x, out);

    (void)n_in; (void)out_size;
}

// round 6
// speedup vs baseline: 1.4025x; 1.4025x over previous
#include <cuda_runtime.h>
#include <math.h>

// Problem constants (fixed shapes)
#define E      768
#define H      12
#define NW     8
#define DK     64
#define KFEAT  16            // 8 cos + 8 sin features
#define KROWS  17            // + bias row
#define PN     (KROWS * E)   // 13056 folded-weight elements

#define TOK_PER_BLK  32
#define MAIN_THREADS 192     // 192 threads x 4 columns = 768

#define RCHUNKS 48
#define RCHUNK  (E / RCHUNKS)   // 16

// Scratch (device globals: allocation-free rule)
__device__ __align__(16) float g_R[PN];                 // folded weights [17][768]
__device__ __align__(16) float g_part[RCHUNKS * PN];    // deterministic partial sums

// ---------------------------------------------------------------------------
// packed fp32x2 helpers (PTX-only, sm_100+) — fma2/pack2 passed in R1/R2
// ---------------------------------------------------------------------------
__device__ __forceinline__ unsigned long long fma2(unsigned long long a,
                                                   unsigned long long b,
                                                   unsigned long long c) {
    unsigned long long d;
    asm("fma.rn.f32x2 %0, %1, %2, %3;" : "=l"(d) : "l"(a), "l"(b), "l"(c));
    return d;
}
__device__ __forceinline__ unsigned long long pack2(float v) {
    unsigned long long d;
    asm("mov.b64 %0, {%1, %1};" : "=l"(d) : "f"(v));
    return d;
}

// ---------------------------------------------------------------------------
// Kernel A (fused build_P + fold): partial R = P @ W_out over r-chunks.
//   P[k][r], r = h*64+d:
//     k in [0,8):   cos(theta[h][k])    * W_proj[h][k][d]
//     k in [8,16): -sin(theta[h][k-8])  * W_proj[h][k-8][d]
//     k == 16:      b_proj[r]
//   grid (6 e-chunks of 128, 48 r-chunks of 16), 128 threads
// ---------------------------------------------------------------------------
__global__ void fold_R_partial_kernel(const float* __restrict__ theta,
                                      const float* __restrict__ W_proj,
                                      const float* __restrict__ b_proj,
                                      const float* __restrict__ W_out) {
    __shared__ float Ps[KROWS][RCHUNK];
    const int e  = blockIdx.x * 128 + threadIdx.x;
    const int r0 = blockIdx.y * RCHUNK;

    // Build the P slab in-block (KROWS*RCHUNK = 272 entries)
    for (int idx = threadIdx.x; idx < KROWS * RCHUNK; idx += 128) {
        int k  = idx / RCHUNK;
        int rr = idx - k * RCHUNK;
        int r  = r0 + rr;
        int h  = r >> 6;
        int d  = r & 63;
        float v;
        if (k < 8) {
            v = cosf(theta[h * NW + k]) * W_proj[(h * NW + k) * DK + d];
        } else if (k < 16) {
            int w = k - 8;
            v = -sinf(theta[h * NW + w]) * W_proj[(h * NW + w) * DK + d];
        } else {
            v = b_proj[r];
        }
        Ps[k][rr] = v;
    }
    __syncthreads();

    // Fully unrolled: 16 independent W_out loads in flight (MLP=16)
    float wo[RCHUNK];
#pragma unroll
    for (int rr = 0; rr < RCHUNK; rr++)
        wo[rr] = __ldg(&W_out[(size_t)(r0 + rr) * E + e]);

    float acc[KROWS];
#pragma unroll
    for (int k = 0; k < KROWS; k++) acc[k] = 0.f;

#pragma unroll
    for (int rr = 0; rr < RCHUNK; rr++) {
#pragma unroll
        for (int k = 0; k < KROWS; k++) acc[k] = fmaf(Ps[k][rr], wo[rr], acc[k]);
    }

    float* dst = g_part + (size_t)blockIdx.y * PN;
#pragma unroll
    for (int k = 0; k < KROWS; k++) dst[k * E + e] = acc[k];
}

// ---------------------------------------------------------------------------
// Kernel B: reduce partials (+ b_out into bias row). Partials are L2-hot.
// ---------------------------------------------------------------------------
__global__ void reduce_R_kernel(const float* __restrict__ b_out) {
    int i = blockIdx.x * blockDim.x + threadIdx.x;
    if (i >= PN) return;
    float s = 0.f;
#pragma unroll
    for (int j = 0; j < RCHUNKS; j++) s += g_part[(size_t)j * PN + i];
    if (i >= 16 * E) s += b_out[i - 16 * E];
    g_R[i] = s;
}

// ---------------------------------------------------------------------------
// Main kernel: per token 8 sincos, then [ntok,16] @ R[16,768] + bias
//   grid ntok/32, 192 threads. Each thread owns 4 ADJACENT columns
//   (2 packed f32x2 pairs -> one STG.128 via __stcs). Features pre-packed
//   in smem. Per token per thread: 8 LDS.128 + 32 FFMA2 + 1 STG.128.
// ---------------------------------------------------------------------------
__global__ void __launch_bounds__(MAIN_THREADS, 3)
qattn_main_kernel(const float* __restrict__ x, float* __restrict__ out) {
    __shared__ unsigned long long s_cs2[TOK_PER_BLK][KFEAT];   // 4 KB

    const int tid   = threadIdx.x;
    const long tok0 = (long)blockIdx.x * TOK_PER_BLK;

    // ---- Phase 1: sincos of x[:, :8], pre-duplicated as f32x2 ----
    if (tid < 4 * TOK_PER_BLK) {
        int t = tid >> 2;            // token 0..31
        int q = tid & 3;             // quarter: 2 features each
        const float2 xv = *(const float2*)(x + (size_t)(tok0 + t) * E + q * 2);
        float s, c;
        sincosf(xv.x, &s, &c);
        s_cs2[t][q * 2 + 0] = pack2(c);  s_cs2[t][8 + q * 2 + 0] = pack2(s);
        sincosf(xv.y, &s, &c);
        s_cs2[t][q * 2 + 1] = pack2(c);  s_cs2[t][8 + q * 2 + 1] = pack2(s);
    }

    // ---- Phase 2: this thread's 4 adjacent columns of folded weights ----
    const int c = 4 * tid;           // columns [c, c+4)
    unsigned long long wlo[KROWS], whi[KROWS];
#pragma unroll
    for (int k = 0; k < KROWS; k++) {
        const ulonglong2 v = *(const ulonglong2*)(g_R + k * E + c);
        wlo[k] = v.x;  whi[k] = v.y;
    }

    __syncthreads();

    // ---- Token loop ----
    const ulonglong2* ap = (const ulonglong2*)s_cs2[0];
    float* op = out + (size_t)tok0 * E + c;
#pragma unroll 2
    for (int t = 0; t < TOK_PER_BLK; t++) {
        ulonglong2 v0 = ap[0], v1 = ap[1], v2 = ap[2], v3 = ap[3];
        unsigned long long alo = fma2(v0.x, wlo[0], wlo[16]);  // bias as init
        unsigned long long ahi = fma2(v0.x, whi[0], whi[16]);
        alo = fma2(v0.y, wlo[1], alo);  ahi = fma2(v0.y, whi[1], ahi);
        alo = fma2(v1.x, wlo[2], alo);  ahi = fma2(v1.x, whi[2], ahi);
        alo = fma2(v1.y, wlo[3], alo);  ahi = fma2(v1.y, whi[3], ahi);
        alo = fma2(v2.x, wlo[4], alo);  ahi = fma2(v2.x, whi[4], ahi);
        alo = fma2(v2.y, wlo[5], alo);  ahi = fma2(v2.y, whi[5], ahi);
        alo = fma2(v3.x, wlo[6], alo);  ahi = fma2(v3.x, whi[6], ahi);
        alo = fma2(v3.y, wlo[7], alo);  ahi = fma2(v3.y, whi[7], ahi);

        ulonglong2 v4 = ap[4], v5 = ap[5], v6 = ap[6], v7 = ap[7];
        alo = fma2(v4.x, wlo[8],  alo); ahi = fma2(v4.x, whi[8],  ahi);
        alo = fma2(v4.y, wlo[9],  alo); ahi = fma2(v4.y, whi[9],  ahi);
        alo = fma2(v5.x, wlo[10], alo); ahi = fma2(v5.x, whi[10], ahi);
        alo = fma2(v5.y, wlo[11], alo); ahi = fma2(v5.y, whi[11], ahi);
        alo = fma2(v6.x, wlo[12], alo); ahi = fma2(v6.x, whi[12], ahi);
        alo = fma2(v6.y, wlo[13], alo); ahi = fma2(v6.y, whi[13], ahi);
        alo = fma2(v7.x, wlo[14], alo); ahi = fma2(v7.x, whi[14], ahi);
        alo = fma2(v7.y, wlo[15], alo); ahi = fma2(v7.y, whi[15], ahi);

        // 128-bit streaming store via intrinsic (STG.E.128 with .cs hint)
        ulonglong2 acc;  acc.x = alo;  acc.y = ahi;
        __stcs((float4*)op, *(float4*)&acc);

        op += E;
        ap += KFEAT / 2;   // next token's feature row
    }
}

// ---------------------------------------------------------------------------
// Launch
// inputs (metadata order): x[B,S,E] f32, theta[H,NW] f32, W_proj[H,NW,DK] f32,
//                          b_proj[H,DK] f32, W_out[E,E] f32, b_out[E] f32
// output: [B,S,E] f32
// ---------------------------------------------------------------------------
extern "C" void kernel_launch(void* const* d_in, const int* in_sizes, int n_in,
                              void* d_out, int out_size) {
    const float* x      = (const float*)d_in[0];
    const float* theta  = (const float*)d_in[1];
    const float* W_proj = (const float*)d_in[2];
    const float* b_proj = (const float*)d_in[3];
    const float* W_out  = (const float*)d_in[4];
    const float* b_out  = (const float*)d_in[5];
    float* out = (float*)d_out;

    const int ntok = in_sizes[0] / E;               // B*S = 32768

    // Prologue: fold weights (recomputed every call — deterministic)
    fold_R_partial_kernel<<<dim3(E / 128, RCHUNKS), 128>>>(theta, W_proj, b_proj, W_out);
    reduce_R_kernel<<<(PN + 255) / 256, 256>>>(b_out);

    // Main pass
    qattn_main_kernel<<<ntok / TOK_PER_BLK, MAIN_THREADS>>>(x, out);

    (void)n_in; (void)out_size;
}